// round 11
// baseline (speedup 1.0000x reference)
#include <cuda_runtime.h>
#include <cuda_bf16.h>

// StandardDeviationPooling: 4x4 window, stride 2, VALID.
// Input:  [64, 1024, 1024, 1] fp32   Output: [64, 511*511] fp32
// std = sqrt(max(E[x^2] - E[x]^2, 0)) per window.
//
// R11: R10 (boustrophedon strips -> strip-boundary re-reads hit L2, DRAM
// traffic at the ~323 MB floor; RPT=14 -> 2368 CTAs = exact 2 waves @ occ 8;
// __stcs stores; rolling 2-row pair sums) with the strip direction hoisted to
// a COMPILE-TIME template parameter: both loop bodies are pure monotone
// pointer walks with zero per-iteration direction selects (R10's runtime
// `asc ? t : RPT-t` cost ~7pts of issue% and ~2.4% of DRAM BW vs R9).

#define H_IN 1024
#define W_IN 1024
#define H_OUT 511
#define W_OUT 511
#define ROWS_PER_THREAD 14

template<bool ASC>
__device__ __forceinline__ void run_strip(
    const float* __restrict__ inb, float* __restrict__ outb,
    int r0, int ic, int oc0, bool has2)
{
    const float inv_n = 1.0f / 16.0f;
    float ps0 = 0.f, ps1 = 0.f, pq0 = 0.f, pq1 = 0.f;

    #pragma unroll
    for (int t = 0; t <= ROWS_PER_THREAD; ++t) {
        const int p    = ASC ? t : (ROWS_PER_THREAD - t);   // compile-time affine
        const int irow = 2 * (r0 + p);
        float cs0 = 0.f, cs1 = 0.f, cq0 = 0.f, cq1 = 0.f;

        if (irow + 1 < H_IN) {
            #pragma unroll
            for (int rr = 0; rr < 2; ++rr) {
                const float* rowp = inb + (size_t)(irow + rr) * W_IN + ic;
                const float4 a = *reinterpret_cast<const float4*>(rowp);
                float4 d;
                if (has2) d = *reinterpret_cast<const float4*>(rowp + 4);
                else      d = make_float4(0.f, 0.f, 0.f, 0.f);

                cs0 += a.x + a.y + a.z + a.w;
                cq0 = fmaf(a.x, a.x, fmaf(a.y, a.y, fmaf(a.z, a.z, fmaf(a.w, a.w, cq0))));
                cs1 += a.z + a.w + d.x + d.y;
                cq1 = fmaf(a.z, a.z, fmaf(a.w, a.w, fmaf(d.x, d.x, fmaf(d.y, d.y, cq1))));
            }
        }

        if (t > 0) {
            // ascending: output row uses pairs (p-1, p)  -> orow = r0 + p - 1
            // descending: output row uses pairs (p, p+1) -> orow = r0 + p
            const int orow = ASC ? (r0 + p - 1) : (r0 + p);
            if (orow < H_OUT) {
                float* orow_p = outb + (size_t)orow * W_OUT;
                {
                    const float s = ps0 + cs0, q = pq0 + cq0;
                    const float m = s * inv_n;
                    __stcs(orow_p + oc0, sqrtf(fmaxf(fmaf(-m, m, q * inv_n), 0.f)));
                }
                if (oc0 + 1 < W_OUT) {
                    const float s = ps1 + cs1, q = pq1 + cq1;
                    const float m = s * inv_n;
                    __stcs(orow_p + oc0 + 1, sqrtf(fmaxf(fmaf(-m, m, q * inv_n), 0.f)));
                }
            }
        }
        ps0 = cs0; ps1 = cs1; pq0 = cq0; pq1 = cq1;
    }
}

__global__ __launch_bounds__(256, 8)
void std_pool_kernel(const float* __restrict__ in, float* __restrict__ out) {
    const int c     = threadIdx.x;                 // col-pair index 0..255
    const int strip = blockIdx.y;
    const int r0    = strip * ROWS_PER_THREAD;
    const int b     = blockIdx.z;

    const float* __restrict__ inb  = in  + (size_t)b * H_IN * W_IN;
    float* __restrict__       outb = out + (size_t)b * H_OUT * W_OUT;

    const int  ic   = 4 * c;                 // first input col
    const bool has2 = (ic + 7) < W_IN;       // second float4 in-bounds (c < 255)
    const int  oc0  = 2 * c;

    if ((strip & 1) == 0) run_strip<true >(inb, outb, r0, ic, oc0, has2);
    else                  run_strip<false>(inb, outb, r0, ic, oc0, has2);
}

extern "C" void kernel_launch(void* const* d_in, const int* in_sizes, int n_in,
                              void* d_out, int out_size) {
    const float* in = (const float*)d_in[0];
    float* out = (float*)d_out;
    (void)in_sizes; (void)n_in; (void)out_size;

    // 256 col-pair threads cover 511 output cols; 37 strips of 14 rows; 64 batches.
    // 37*64 = 2368 CTAs = exactly 2 waves at 8 CTAs/SM x 148 SMs.
    dim3 block(256, 1, 1);
    dim3 grid(1, (H_OUT + ROWS_PER_THREAD - 1) / ROWS_PER_THREAD, 64);
    std_pool_kernel<<<grid, block>>>(in, out);
}

// round 12
// speedup vs baseline: 1.0115x; 1.0115x over previous
#include <cuda_runtime.h>
#include <cuda_bf16.h>

// StandardDeviationPooling: 4x4 window, stride 2, VALID.
// Input:  [64, 1024, 1024, 1] fp32   Output: [64, 511*511] fp32
// std = sqrt(max(E[x^2] - E[x]^2, 0)) per window.
//
// R12: R11 (boustrophedon strips -> boundary re-reads hit L2, traffic at the
// ~316-323 MB floor; compile-time strip direction; RPT=14 -> 2368 CTAs =
// exact 2 waves @ occ 8; __stcs stores; rolling 2-row pair sums) + FULL/TAIL
// strip specialization: strips 0..35 run a guard-free body (no irow/orow
// bounds checks -- they provably cannot fire there), only strip 36 takes the
// guarded path. Fewer ISETP/BRA per load batch -> more issue slots for LDG.

#define H_IN 1024
#define W_IN 1024
#define H_OUT 511
#define W_OUT 511
#define ROWS_PER_THREAD 14
#define NSTRIPS 37           // ceil(511/14); strip 36 is the tail

template<bool ASC, bool FULL>
__device__ __forceinline__ void run_strip(
    const float* __restrict__ inb, float* __restrict__ outb,
    int r0, int ic, int oc0, bool has2)
{
    const float inv_n = 1.0f / 16.0f;
    float ps0 = 0.f, ps1 = 0.f, pq0 = 0.f, pq1 = 0.f;

    #pragma unroll
    for (int t = 0; t <= ROWS_PER_THREAD; ++t) {
        const int p    = ASC ? t : (ROWS_PER_THREAD - t);   // compile-time affine
        const int irow = 2 * (r0 + p);
        float cs0 = 0.f, cs1 = 0.f, cq0 = 0.f, cq1 = 0.f;

        if (FULL || (irow + 1 < H_IN)) {
            #pragma unroll
            for (int rr = 0; rr < 2; ++rr) {
                const float* rowp = inb + (size_t)(irow + rr) * W_IN + ic;
                const float4 a = *reinterpret_cast<const float4*>(rowp);
                float4 d;
                if (has2) d = *reinterpret_cast<const float4*>(rowp + 4);
                else      d = make_float4(0.f, 0.f, 0.f, 0.f);

                cs0 += a.x + a.y + a.z + a.w;
                cq0 = fmaf(a.x, a.x, fmaf(a.y, a.y, fmaf(a.z, a.z, fmaf(a.w, a.w, cq0))));
                cs1 += a.z + a.w + d.x + d.y;
                cq1 = fmaf(a.z, a.z, fmaf(a.w, a.w, fmaf(d.x, d.x, fmaf(d.y, d.y, cq1))));
            }
        }

        if (t > 0) {
            // ascending: output row uses pairs (p-1, p)  -> orow = r0 + p - 1
            // descending: output row uses pairs (p, p+1) -> orow = r0 + p
            const int orow = ASC ? (r0 + p - 1) : (r0 + p);
            if (FULL || (orow < H_OUT)) {
                float* orow_p = outb + (size_t)orow * W_OUT;
                {
                    const float s = ps0 + cs0, q = pq0 + cq0;
                    const float m = s * inv_n;
                    __stcs(orow_p + oc0, sqrtf(fmaxf(fmaf(-m, m, q * inv_n), 0.f)));
                }
                if (oc0 + 1 < W_OUT) {
                    const float s = ps1 + cs1, q = pq1 + cq1;
                    const float m = s * inv_n;
                    __stcs(orow_p + oc0 + 1, sqrtf(fmaxf(fmaf(-m, m, q * inv_n), 0.f)));
                }
            }
        }
        ps0 = cs0; ps1 = cs1; pq0 = cq0; pq1 = cq1;
    }
}

__global__ __launch_bounds__(256, 8)
void std_pool_kernel(const float* __restrict__ in, float* __restrict__ out) {
    const int c     = threadIdx.x;                 // col-pair index 0..255
    const int strip = blockIdx.y;
    const int r0    = strip * ROWS_PER_THREAD;
    const int b     = blockIdx.z;

    const float* __restrict__ inb  = in  + (size_t)b * H_IN * W_IN;
    float* __restrict__       outb = out + (size_t)b * H_OUT * W_OUT;

    const int  ic   = 4 * c;                 // first input col
    const bool has2 = (ic + 7) < W_IN;       // second float4 in-bounds (c < 255)
    const int  oc0  = 2 * c;

    const bool full = (strip != NSTRIPS - 1);   // only the last strip needs guards
    if ((strip & 1) == 0) {
        if (full) run_strip<true,  true >(inb, outb, r0, ic, oc0, has2);
        else      run_strip<true,  false>(inb, outb, r0, ic, oc0, has2);
    } else {
        if (full) run_strip<false, true >(inb, outb, r0, ic, oc0, has2);
        else      run_strip<false, false>(inb, outb, r0, ic, oc0, has2);
    }
}

extern "C" void kernel_launch(void* const* d_in, const int* in_sizes, int n_in,
                              void* d_out, int out_size) {
    const float* in = (const float*)d_in[0];
    float* out = (float*)d_out;
    (void)in_sizes; (void)n_in; (void)out_size;

    // 256 col-pair threads cover 511 output cols; 37 strips of 14 rows; 64 batches.
    // 37*64 = 2368 CTAs = exactly 2 waves at 8 CTAs/SM x 148 SMs.
    dim3 block(256, 1, 1);
    dim3 grid(1, NSTRIPS, 64);
    std_pool_kernel<<<grid, block>>>(in, out);
}